// round 12
// baseline (speedup 1.0000x reference)
#include <cuda_runtime.h>
#include <cuda_fp16.h>
#include <math.h>

// Problem constants: B=2, H=16, S=2048, D=64
#define Bn   2
#define Hn   16
#define Sn   2048
#define Dn   64
#define BM   64            // q rows per CTA (4 warps x m16)
#define BN   64
#define NT   (Sn / BN)     // 32 tiles
#define NTHR 128
#define NEGF (-3.402823466e38f)
#define SCALE2 0.180336880f   // 0.125 * log2(e)

#define LDK  68      // K tile row stride (floats), natural [key][d]
#define LDQ  68      // Q staging row stride (floats)
#define LDVH 80      // V fp16 tile row stride (halves), [d][key-permuted]

// smem layout (float offsets)
#define K0_F   0                       // K stage 0: 64*68 = 4352 f
#define K1_F   4352                    // K stage 1
#define VH_F   8704                    // V fp16: 64*80 halves = 2560 f
#define SCR_F  11264                   // V fp32 scratch / Q staging: 4352 f
#define SMEM_FLOATS (SCR_F + 4352)     // 15616
#define SMEM_BYTES  (SMEM_FLOATS * 4)  // 62464 B -> 3 CTAs/SM fits

// mask dtype mode: 0 = uint8 bytes, 1 = int32 0/1, 2 = float32 0.0/1.0
__device__ int g_mask_mode;

__global__ void probe_mask_kernel(const unsigned int* __restrict__ m)
{
    __shared__ int s_i32ok, s_f32ok;
    if (threadIdx.x == 0) { s_i32ok = 1; s_f32ok = 1; }
    __syncthreads();
    int i32ok = 1, f32ok = 1;
    for (int i = threadIdx.x; i < 16384; i += blockDim.x) {
        unsigned int w = m[i];
        if (w > 1u)                      i32ok = 0;
        if (w != 0u && w != 0x3F800000u) f32ok = 0;
    }
    if (!i32ok) atomicAnd(&s_i32ok, 0);
    if (!f32ok) atomicAnd(&s_f32ok, 0);
    __syncthreads();
    if (threadIdx.x == 0)
        g_mask_mode = s_i32ok ? 1 : (s_f32ok ? 2 : 0);
}

__device__ __forceinline__ unsigned f2tf(float x)
{
    unsigned u;
    asm("cvt.rna.tf32.f32 %0, %1;" : "=r"(u) : "f"(x));
    return u;
}

__device__ __forceinline__ float ex2(float x)
{
    float r;
    asm("ex2.approx.f32 %0, %1;" : "=f"(r) : "f"(x));
    return r;
}

__device__ __forceinline__ void cpasync16(unsigned smem, const void* gptr)
{
    asm volatile("cp.async.cg.shared.global [%0], [%1], 16;\n"
                 :: "r"(smem), "l"(gptr));
}

__device__ __forceinline__ void mma_tf32(float* d, const unsigned* a,
                                         unsigned b0, unsigned b1)
{
    asm volatile(
        "mma.sync.aligned.m16n8k8.row.col.f32.tf32.tf32.f32 "
        "{%0,%1,%2,%3}, {%4,%5,%6,%7}, {%8,%9}, {%0,%1,%2,%3};"
        : "+f"(d[0]), "+f"(d[1]), "+f"(d[2]), "+f"(d[3])
        : "r"(a[0]), "r"(a[1]), "r"(a[2]), "r"(a[3]), "r"(b0), "r"(b1));
}

__device__ __forceinline__ void mma_f16(float* d, const unsigned* a,
                                        unsigned b0, unsigned b1)
{
    asm volatile(
        "mma.sync.aligned.m16n8k16.row.col.f32.f16.f16.f32 "
        "{%0,%1,%2,%3}, {%4,%5,%6,%7}, {%8,%9}, {%0,%1,%2,%3};"
        : "+f"(d[0]), "+f"(d[1]), "+f"(d[2]), "+f"(d[3])
        : "r"(a[0]), "r"(a[1]), "r"(a[2]), "r"(a[3]), "r"(b0), "r"(b1));
}

__device__ __forceinline__ unsigned packh2(float x, float y)
{
    __half2 h = __floats2half2_rn(x, y);
    return *reinterpret_cast<unsigned*>(&h);
}

__global__ __launch_bounds__(NTHR, 3)
void attn_mma_kernel(const float* __restrict__ Q,
                     const float* __restrict__ K,
                     const float* __restrict__ V,
                     const void* __restrict__ Mraw,
                     float* __restrict__ O)
{
    extern __shared__ float sm[];

    const int bh   = blockIdx.y;
    const int b    = bh >> 4;
    const int q0   = blockIdx.x * BM;
    const int tid  = threadIdx.x;
    const int warp = tid >> 5;            // 0..3
    const int lane = tid & 31;
    const int g    = lane >> 2;           // row group 0..7
    const int c    = lane & 3;            // col pair  0..3
    const int r0   = warp * 16;
    const int mode = g_mask_mode;

    const float* Qg = Q + (size_t)bh * Sn * Dn;
    const float* Kg = K + (size_t)bh * Sn * Dn;
    const float* Vg = V + (size_t)bh * Sn * Dn;
    float*       Og = O + (size_t)bh * Sn * Dn;

    const unsigned char* M8  = (const unsigned char*)Mraw + (size_t)b * Sn * Sn;
    const int*           M32 = (const int*)Mraw           + (size_t)b * Sn * Sn;
    const float*         Mf  = (const float*)Mraw         + (size_t)b * Sn * Sn;

    const int rowA = q0 + r0 + g;    // global q row of c0/c1
    const int rowB = rowA + 8;       // global q row of c2/c3

    // loader mappings (128 threads): K and V scratch use the same map
    const int kkey = tid >> 1;             // 0..63 (row)
    const int kdc  = (tid & 1) * 32;       // 0 or 32 (8 x 16B chunks)
    const int vkp  = tid & 31;             // key pair 2vkp, 2vkp+1 (convert pass)
    const int vd0  = (tid >> 5) * 16;      // 16 d's per thread (convert pass)
    const int vkgbase = (vkp >> 3) * 16;
    const int vpb     = 4 * (vkp & 3) + 2 * ((vkp >> 2) & 1);

    const unsigned smem_u32 = (unsigned)__cvta_generic_to_shared(sm);

    // async loaders: K tile -> K stage sb; V tile -> fp32 scratch
    auto asyncK = [&](int kt, int sb) {
        const unsigned dstb = smem_u32 +
            (unsigned)((sb ? K1_F : K0_F) + kkey * LDK + kdc) * 4u;
        const float* src = Kg + (size_t)(kt + kkey) * Dn + kdc;
#pragma unroll
        for (int i = 0; i < 8; i++)
            cpasync16(dstb + 16u * i, src + 4 * i);
    };
    auto asyncV = [&](int kt) {
        const unsigned dstb = smem_u32 + (unsigned)(SCR_F + kkey * LDK + kdc) * 4u;
        const float* src = Vg + (size_t)(kt + kkey) * Dn + kdc;
#pragma unroll
        for (int i = 0; i < 8; i++)
            cpasync16(dstb + 16u * i, src + 4 * i);
    };

    // ---- prologue: stage Q into scratch region, extract fragments ----
    {
        float* Qst = sm + SCR_F;
        const int r  = tid >> 1;
        const int dc = (tid & 1) * 32;
        const float* src = Qg + (size_t)(q0 + r) * Dn + dc;
#pragma unroll
        for (int i = 0; i < 8; i++)
            *(float4*)(Qst + r * LDQ + dc + 4 * i) = *(const float4*)(src + 4 * i);
    }
    __syncthreads();

    unsigned qa[8][4];
    {
        const float* Qst = sm + SCR_F;
        const int row = r0 + g;
#pragma unroll
        for (int kf = 0; kf < 8; kf++) {
            const int col = 8 * kf + c;
            qa[kf][0] = f2tf(Qst[row * LDQ + col]);
            qa[kf][1] = f2tf(Qst[(row + 8) * LDQ + col]);
            qa[kf][2] = f2tf(Qst[row * LDQ + col + 4]);
            qa[kf][3] = f2tf(Qst[(row + 8) * LDQ + col + 4]);
        }
    }
    __syncthreads();   // all Q reads done before V0 overwrites scratch

    float o[8][4];
#pragma unroll
    for (int i = 0; i < 8; i++)
#pragma unroll
        for (int j = 0; j < 4; j++) o[i][j] = 0.f;
    float mrow0 = -INFINITY, mrow1 = -INFINITY;   // raw-score units
    float lrow0 = 0.f, lrow1 = 0.f;

    // ---- preload tile 0: K -> stage 0, V fp32 -> scratch ----
    asyncK(0, 0);
    asyncV(0);
    asm volatile("cp.async.commit_group;\n");
    asm volatile("cp.async.wait_group 0;\n" ::: "memory");
    __syncthreads();

    for (int t = 0; t < NT; t++) {
        const int kt = t * BN;
        unsigned* Ksu = (unsigned*)(sm + ((t & 1) ? K1_F : K0_F));
        __half*   Vs  = (__half*)(sm + VH_F);

        // ---- convert pass: V(t) fp32 scratch -> fp16 key-permuted buffer ----
        {
            const float* s0 = sm + SCR_F + (2 * vkp) * LDK + vd0;
            const float* s1 = s0 + LDK;
            float4 a0 = *(const float4*)(s0),      a1 = *(const float4*)(s0 + 4);
            float4 a2 = *(const float4*)(s0 + 8),  a3 = *(const float4*)(s0 + 12);
            float4 b0 = *(const float4*)(s1),      b1 = *(const float4*)(s1 + 4);
            float4 b2 = *(const float4*)(s1 + 8),  b3 = *(const float4*)(s1 + 12);
            const float r0v[16] = {a0.x,a0.y,a0.z,a0.w, a1.x,a1.y,a1.z,a1.w,
                                   a2.x,a2.y,a2.z,a2.w, a3.x,a3.y,a3.z,a3.w};
            const float r1v[16] = {b0.x,b0.y,b0.z,b0.w, b1.x,b1.y,b1.z,b1.w,
                                   b2.x,b2.y,b2.z,b2.w, b3.x,b3.y,b3.z,b3.w};
#pragma unroll
            for (int i = 0; i < 16; i++)
                *(__half2*)(Vs + (vd0 + i) * LDVH + vkgbase + vpb) =
                    __floats2half2_rn(r0v[i], r1v[i]);
        }
        __syncthreads();   // convert reads/writes complete

        // ---- prefetch NEXT tile: K + V fp32 via cp.async ----
        if (t + 1 < NT) {
            asyncK(kt + BN, (t + 1) & 1);
            asyncV(kt + BN);
            asm volatile("cp.async.commit_group;\n");
        }

        // ---- prefetch mask for THIS tile ----
        int2  m32a[8], m32b[8];
        unsigned short m8a[8], m8b[8];
        float2 mfa[8], mfb[8];
        if (mode == 1) {
#pragma unroll
            for (int n = 0; n < 8; n++) {
                const int colb = kt + 8 * n + 2 * c;
                m32a[n] = *(const int2*)(M32 + (size_t)rowA * Sn + colb);
                m32b[n] = *(const int2*)(M32 + (size_t)rowB * Sn + colb);
            }
        } else if (mode == 0) {
#pragma unroll
            for (int n = 0; n < 8; n++) {
                const int colb = kt + 8 * n + 2 * c;
                m8a[n] = *(const unsigned short*)(M8 + (size_t)rowA * Sn + colb);
                m8b[n] = *(const unsigned short*)(M8 + (size_t)rowB * Sn + colb);
            }
        } else {
#pragma unroll
            for (int n = 0; n < 8; n++) {
                const int colb = kt + 8 * n + 2 * c;
                mfa[n] = *(const float2*)(Mf + (size_t)rowA * Sn + colb);
                mfb[n] = *(const float2*)(Mf + (size_t)rowB * Sn + colb);
            }
        }

        // ---- GEMM1: S = Q K^T (tf32), kf outer (independent accumulators) ----
        float s[8][4];
#pragma unroll
        for (int n = 0; n < 8; n++)
            s[n][0] = s[n][1] = s[n][2] = s[n][3] = 0.f;

#pragma unroll
        for (int kf = 0; kf < 8; kf++) {
            unsigned kq[8][2];
#pragma unroll
            for (int n = 0; n < 8; n++) {
                const unsigned* kb = Ksu + (8 * n + g) * LDK + 8 * kf + c;
                kq[n][0] = kb[0];
                kq[n][1] = kb[4];
            }
#pragma unroll
            for (int n = 0; n < 8; n++)
                mma_tf32(s[n], qa[kf], kq[n][0], kq[n][1]);
        }

        // ---- apply mask (BEFORE scale; scale folded into exp) ----
        if (mode == 1) {
#pragma unroll
            for (int n = 0; n < 8; n++) {
                if (m32a[n].x) s[n][0] = NEGF;  if (m32a[n].y) s[n][1] = NEGF;
                if (m32b[n].x) s[n][2] = NEGF;  if (m32b[n].y) s[n][3] = NEGF;
            }
        } else if (mode == 0) {
#pragma unroll
            for (int n = 0; n < 8; n++) {
                if (m8a[n] & 0xFF) s[n][0] = NEGF;  if (m8a[n] >> 8) s[n][1] = NEGF;
                if (m8b[n] & 0xFF) s[n][2] = NEGF;  if (m8b[n] >> 8) s[n][3] = NEGF;
            }
        } else {
#pragma unroll
            for (int n = 0; n < 8; n++) {
                if (mfa[n].x != 0.f) s[n][0] = NEGF;  if (mfa[n].y != 0.f) s[n][1] = NEGF;
                if (mfb[n].x != 0.f) s[n][2] = NEGF;  if (mfb[n].y != 0.f) s[n][3] = NEGF;
            }
        }

        // ---- online softmax on raw scores ----
        float mt0 = -INFINITY, mt1 = -INFINITY;
#pragma unroll
        for (int n = 0; n < 8; n++) {
            mt0 = fmaxf(mt0, fmaxf(s[n][0], s[n][1]));
            mt1 = fmaxf(mt1, fmaxf(s[n][2], s[n][3]));
        }
        mt0 = fmaxf(mt0, __shfl_xor_sync(0xffffffffu, mt0, 1));
        mt0 = fmaxf(mt0, __shfl_xor_sync(0xffffffffu, mt0, 2));
        mt1 = fmaxf(mt1, __shfl_xor_sync(0xffffffffu, mt1, 1));
        mt1 = fmaxf(mt1, __shfl_xor_sync(0xffffffffu, mt1, 2));

        const float mn0 = fmaxf(mrow0, mt0);
        const float mn1 = fmaxf(mrow1, mt1);
        const float cr0 = ex2((mrow0 - mn0) * SCALE2);
        const float cr1 = ex2((mrow1 - mn1) * SCALE2);
        const float nm0 = -mn0 * SCALE2;
        const float nm1 = -mn1 * SCALE2;

#pragma unroll
        for (int n = 0; n < 8; n++) {
            s[n][0] = ex2(fmaf(s[n][0], SCALE2, nm0));
            s[n][1] = ex2(fmaf(s[n][1], SCALE2, nm0));
            s[n][2] = ex2(fmaf(s[n][2], SCALE2, nm1));
            s[n][3] = ex2(fmaf(s[n][3], SCALE2, nm1));
        }

        if (!__all_sync(0xffffffffu, (cr0 == 1.f) && (cr1 == 1.f))) {
#pragma unroll
            for (int n = 0; n < 8; n++) {
                o[n][0] *= cr0; o[n][1] *= cr0;
                o[n][2] *= cr1; o[n][3] *= cr1;
            }
        }

        // ---- GEMM2: O += P V (fp16), P from C-frags in-register ----
#pragma unroll
        for (int kg = 0; kg < 4; kg++) {
            unsigned pa[4];
            pa[0] = packh2(s[2 * kg][0],     s[2 * kg][1]);
            pa[1] = packh2(s[2 * kg][2],     s[2 * kg][3]);
            pa[2] = packh2(s[2 * kg + 1][0], s[2 * kg + 1][1]);
            pa[3] = packh2(s[2 * kg + 1][2], s[2 * kg + 1][3]);
#pragma unroll
            for (int nd = 0; nd < 8; nd++) {
                uint2 bb = *(const uint2*)(Vs + (8 * nd + g) * LDVH + 16 * kg + 4 * c);
                mma_f16(o[nd], pa, bb.x, bb.y);
            }
        }

        // ---- deferred row-sum reduction (overlaps GEMM2 latency) ----
        {
            float p0 = 0.f, p1 = 0.f;
#pragma unroll
            for (int n = 0; n < 8; n++) {
                p0 += s[n][0] + s[n][1];
                p1 += s[n][2] + s[n][3];
            }
            p0 += __shfl_xor_sync(0xffffffffu, p0, 1);
            p0 += __shfl_xor_sync(0xffffffffu, p0, 2);
            p1 += __shfl_xor_sync(0xffffffffu, p1, 1);
            p1 += __shfl_xor_sync(0xffffffffu, p1, 2);
            lrow0 = lrow0 * cr0 + p0;
            lrow1 = lrow1 * cr1 + p1;
            mrow0 = mn0;  mrow1 = mn1;
        }

        // ---- wait for next tile's K + V, then fence the stage swap ----
        if (t + 1 < NT)
            asm volatile("cp.async.wait_group 0;\n" ::: "memory");
        __syncthreads();
    }

    // ---- epilogue: normalize + store ----
    const float inv0 = 1.f / lrow0;
    const float inv1 = 1.f / lrow1;
#pragma unroll
    for (int nd = 0; nd < 8; nd++) {
        const int dcol = 8 * nd + 2 * c;
        float2 w0 = make_float2(o[nd][0] * inv0, o[nd][1] * inv0);
        float2 w1 = make_float2(o[nd][2] * inv1, o[nd][3] * inv1);
        *(float2*)(Og + (size_t)rowA * Dn + dcol) = w0;
        *(float2*)(Og + (size_t)rowB * Dn + dcol) = w1;
    }
}

extern "C" void kernel_launch(void* const* d_in, const int* in_sizes, int n_in,
                              void* d_out, int out_size)
{
    const float* Q = (const float*)d_in[0];
    const float* K = (const float*)d_in[1];
    const float* V = (const float*)d_in[2];
    const void*  M = (const void*)d_in[3];
    float* O = (float*)d_out;

    cudaFuncSetAttribute(attn_mma_kernel,
                         cudaFuncAttributeMaxDynamicSharedMemorySize, SMEM_BYTES);

    probe_mask_kernel<<<1, 256>>>((const unsigned int*)M);

    dim3 grid(Sn / BM, Bn * Hn);   // (32, 32)
    attn_mma_kernel<<<grid, NTHR, SMEM_BYTES>>>(Q, K, V, M, O);
}

// round 14
// speedup vs baseline: 1.4843x; 1.4843x over previous
#include <cuda_runtime.h>
#include <cuda_fp16.h>
#include <math.h>

// Problem constants: B=2, H=16, S=2048, D=64
#define Bn   2
#define Hn   16
#define Sn   2048
#define Dn   64
#define BM   64            // q rows per CTA (4 warps x m16)
#define BN   64
#define NT   (Sn / BN)     // 32 tiles
#define NTHR 128
#define NEGF (-3.402823466e38f)
#define SCALE2 0.180336880f   // 0.125 * log2(e)

#define LDQ  68      // Q staging row stride (floats)
#define LDK  68      // K tile row stride (floats), natural [key][d]
#define LDVH 80      // V tile row stride (halves), [d][key-permuted]
#define KS_F 4352    // floats: K stage size (64*68)
#define STAGE_F 6912 // floats per stage: K 4352 + V 2560 (64*80 halves)
#define SMEM_BYTES (2 * STAGE_F * 4)   // 55296 per CTA -> 3 CTAs/SM fits (166KB)

#define MASK_WORDS_PER_ROW (Sn / 32)   // 64

// mask dtype mode: 0 = uint8 bytes, 1 = int32 0/1, 2 = float32 0.0/1.0
__device__ int g_mask_mode;
// packed mask bits: [b][row][word], bit j of word w = mask[b][row][32w+j]
__device__ unsigned g_mask_bits[Bn * Sn * MASK_WORDS_PER_ROW];

__global__ void probe_mask_kernel(const unsigned int* __restrict__ m)
{
    __shared__ int s_i32ok, s_f32ok;
    if (threadIdx.x == 0) { s_i32ok = 1; s_f32ok = 1; }
    __syncthreads();
    int i32ok = 1, f32ok = 1;
    for (int i = threadIdx.x; i < 16384; i += blockDim.x) {
        unsigned int w = m[i];
        if (w > 1u)                      i32ok = 0;
        if (w != 0u && w != 0x3F800000u) f32ok = 0;
    }
    if (!i32ok) atomicAnd(&s_i32ok, 0);
    if (!f32ok) atomicAnd(&s_f32ok, 0);
    __syncthreads();
    if (threadIdx.x == 0)
        g_mask_mode = s_i32ok ? 1 : (s_f32ok ? 2 : 0);
}

__global__ void pack_mask_kernel(const void* __restrict__ Mraw)
{
    const int mode = g_mask_mode;
    const int lane = threadIdx.x & 31;
    const size_t nwords = (size_t)Bn * Sn * MASK_WORDS_PER_ROW;
    const size_t nwarps = (size_t)(gridDim.x * blockDim.x) >> 5;
    for (size_t w = ((size_t)blockIdx.x * blockDim.x + threadIdx.x) >> 5;
         w < nwords; w += nwarps) {
        const size_t e = w * 32 + lane;
        bool msk;
        if (mode == 1)      msk = ((const int*)Mraw)[e] != 0;
        else if (mode == 0) msk = ((const unsigned char*)Mraw)[e] != 0;
        else                msk = ((const float*)Mraw)[e] != 0.f;
        unsigned bits = __ballot_sync(0xffffffffu, msk);
        if (lane == 0) g_mask_bits[w] = bits;
    }
}

__device__ __forceinline__ unsigned f2tf(float x)
{
    unsigned u;
    asm("cvt.rna.tf32.f32 %0, %1;" : "=r"(u) : "f"(x));
    return u;
}

__device__ __forceinline__ float ex2(float x)
{
    float r;
    asm("ex2.approx.f32 %0, %1;" : "=f"(r) : "f"(x));
    return r;
}

__device__ __forceinline__ void cpasync16(unsigned smem, const void* gptr)
{
    asm volatile("cp.async.cg.shared.global [%0], [%1], 16;\n"
                 :: "r"(smem), "l"(gptr));
}

__device__ __forceinline__ void mma_tf32(float* d, const unsigned* a,
                                         unsigned b0, unsigned b1)
{
    asm volatile(
        "mma.sync.aligned.m16n8k8.row.col.f32.tf32.tf32.f32 "
        "{%0,%1,%2,%3}, {%4,%5,%6,%7}, {%8,%9}, {%0,%1,%2,%3};"
        : "+f"(d[0]), "+f"(d[1]), "+f"(d[2]), "+f"(d[3])
        : "r"(a[0]), "r"(a[1]), "r"(a[2]), "r"(a[3]), "r"(b0), "r"(b1));
}

__device__ __forceinline__ void mma_f16(float* d, const unsigned* a,
                                        unsigned b0, unsigned b1)
{
    asm volatile(
        "mma.sync.aligned.m16n8k16.row.col.f32.f16.f16.f32 "
        "{%0,%1,%2,%3}, {%4,%5,%6,%7}, {%8,%9}, {%0,%1,%2,%3};"
        : "+f"(d[0]), "+f"(d[1]), "+f"(d[2]), "+f"(d[3])
        : "r"(a[0]), "r"(a[1]), "r"(a[2]), "r"(a[3]), "r"(b0), "r"(b1));
}

__device__ __forceinline__ unsigned packh2(float x, float y)
{
    __half2 h = __floats2half2_rn(x, y);
    return *reinterpret_cast<unsigned*>(&h);
}

__global__ __launch_bounds__(NTHR, 3)
void attn_mma_kernel(const float* __restrict__ Q,
                     const float* __restrict__ K,
                     const float* __restrict__ V,
                     float* __restrict__ O)
{
    extern __shared__ float sm[];
    float* Qst = sm;                      // Q staging (overlaps stages)

    const int bh   = blockIdx.y;
    const int b    = bh >> 4;
    const int q0   = blockIdx.x * BM;
    const int tid  = threadIdx.x;
    const int warp = tid >> 5;            // 0..3
    const int lane = tid & 31;
    const int g    = lane >> 2;           // row group 0..7
    const int c    = lane & 3;            // col pair  0..3
    const int r0   = warp * 16;

    const float* Qg = Q + (size_t)bh * Sn * Dn;
    const float* Kg = K + (size_t)bh * Sn * Dn;
    const float* Vg = V + (size_t)bh * Sn * Dn;
    float*       Og = O + (size_t)bh * Sn * Dn;

    const int rowA = q0 + r0 + g;    // global q row of c0/c1
    const int rowB = rowA + 8;       // global q row of c2/c3

    const unsigned* MbA = g_mask_bits +
        ((size_t)b * Sn + rowA) * MASK_WORDS_PER_ROW;
    const unsigned* MbB = g_mask_bits +
        ((size_t)b * Sn + rowB) * MASK_WORDS_PER_ROW;

    // loader mappings (128 threads)
    const int kkey = tid >> 1;             // 0..63 (K cp.async row)
    const int kdc  = (tid & 1) * 32;       // 0 or 32 (8 x 16B chunks)
    const int vkp  = tid & 31;             // key pair 2vkp,2vkp+1
    const int vd0  = (tid >> 5) * 16;      // 16 d's per thread
    const int vkgbase = (vkp >> 3) * 16;
    const int vpb     = 4 * (vkp & 3) + 2 * ((vkp >> 2) & 1);

    const unsigned smem_u32 = (unsigned)__cvta_generic_to_shared(sm);

    // ---- stage Q tile to smem (natural [r][d]) ----
    {
        const int r  = tid >> 1;           // 0..63
        const int dc = (tid & 1) * 32;
        const float* src = Qg + (size_t)(q0 + r) * Dn + dc;
#pragma unroll
        for (int i = 0; i < 8; i++)
            *(float4*)(Qst + r * LDQ + dc + 4 * i) = *(const float4*)(src + 4 * i);
    }
    __syncthreads();

    // ---- Q A-fragments (tf32), persistent in registers ----
    unsigned qa[8][4];
    {
        const int row = r0 + g;
#pragma unroll
        for (int kf = 0; kf < 8; kf++) {
            const int col = 8 * kf + c;
            qa[kf][0] = f2tf(Qst[row * LDQ + col]);
            qa[kf][1] = f2tf(Qst[(row + 8) * LDQ + col]);
            qa[kf][2] = f2tf(Qst[row * LDQ + col + 4]);
            qa[kf][3] = f2tf(Qst[(row + 8) * LDQ + col + 4]);
        }
    }
    __syncthreads();

    float o[8][4];
#pragma unroll
    for (int i = 0; i < 8; i++)
#pragma unroll
        for (int j = 0; j < 4; j++) o[i][j] = 0.f;
    float mrow0 = -INFINITY, mrow1 = -INFINITY;   // raw-score units
    float lrow0 = 0.f, lrow1 = 0.f;

    // V staging registers (32 floats)
    float4 va[4], vb[4];

    auto asyncK = [&](int kt, int sb) {
        const unsigned dstb = smem_u32 + (unsigned)(sb * STAGE_F + kkey * LDK + kdc) * 4u;
        const float* src = Kg + (size_t)(kt + kkey) * Dn + kdc;
#pragma unroll
        for (int i = 0; i < 8; i++)
            cpasync16(dstb + 16u * i, src + 4 * i);
        asm volatile("cp.async.commit_group;\n");
    };
    auto loadV = [&](int kt) {
        const float* s0 = Vg + (size_t)(kt + 2 * vkp) * Dn + vd0;
        const float* s1 = s0 + Dn;
#pragma unroll
        for (int i = 0; i < 4; i++) {
            va[i] = *(const float4*)(s0 + 4 * i);
            vb[i] = *(const float4*)(s1 + 4 * i);
        }
    };
    auto storeV = [&](__half* Vs) {
        const float* r0v = (const float*)va;
        const float* r1v = (const float*)vb;
#pragma unroll
        for (int i = 0; i < 16; i++)
            *(__half2*)(Vs + (vd0 + i) * LDVH + vkgbase + vpb) =
                __floats2half2_rn(r0v[i], r1v[i]);
    };

    // ---- preload tile 0 ----
    asyncK(0, 0);
    loadV(0);
    storeV((__half*)(sm + KS_F));
    asm volatile("cp.async.wait_group 0;\n" ::: "memory");
    __syncthreads();

    for (int t = 0; t < NT; t++) {
        const int kt = t * BN;
        unsigned* Ksu = (unsigned*)(sm + (t & 1) * STAGE_F);
        __half*   Vs  = (__half*)(sm + (t & 1) * STAGE_F + KS_F);

        // ---- prefetch packed mask bits for THIS tile (2 x LDG.64) ----
        const uint2 wa = *(const uint2*)(MbA + 2 * t);
        const uint2 wb = *(const uint2*)(MbB + 2 * t);

        // ---- prefetch NEXT tile: K via cp.async, V into regs ----
        if (t + 1 < NT) {
            asyncK(kt + BN, (t + 1) & 1);
            loadV(kt + BN);
        }

        // ---- GEMM1: S = Q K^T (tf32), kf outer (independent accumulators) ----
        float s[8][4];
#pragma unroll
        for (int n = 0; n < 8; n++)
            s[n][0] = s[n][1] = s[n][2] = s[n][3] = 0.f;

#pragma unroll
        for (int kf = 0; kf < 8; kf++) {
            unsigned kq[8][2];
#pragma unroll
            for (int n = 0; n < 8; n++) {
                const unsigned* kb = Ksu + (8 * n + g) * LDK + 8 * kf + c;
                kq[n][0] = kb[0];
                kq[n][1] = kb[4];
            }
#pragma unroll
            for (int n = 0; n < 8; n++)
                mma_tf32(s[n], qa[kf], kq[n][0], kq[n][1]);
        }

        // ---- apply mask via bit tests (BEFORE scale; scale folded in exp) ----
#pragma unroll
        for (int n = 0; n < 8; n++) {
            const unsigned WA = (n < 4) ? wa.x : wa.y;
            const unsigned WB = (n < 4) ? wb.x : wb.y;
            const int sh = 8 * (n & 3) + 2 * c;
            if ((WA >> sh) & 1u) s[n][0] = NEGF;
            if ((WA >> sh) & 2u) s[n][1] = NEGF;
            if ((WB >> sh) & 1u) s[n][2] = NEGF;
            if ((WB >> sh) & 2u) s[n][3] = NEGF;
        }

        // ---- online softmax on raw scores ----
        float mt0 = -INFINITY, mt1 = -INFINITY;
#pragma unroll
        for (int n = 0; n < 8; n++) {
            mt0 = fmaxf(mt0, fmaxf(s[n][0], s[n][1]));
            mt1 = fmaxf(mt1, fmaxf(s[n][2], s[n][3]));
        }
        mt0 = fmaxf(mt0, __shfl_xor_sync(0xffffffffu, mt0, 1));
        mt0 = fmaxf(mt0, __shfl_xor_sync(0xffffffffu, mt0, 2));
        mt1 = fmaxf(mt1, __shfl_xor_sync(0xffffffffu, mt1, 1));
        mt1 = fmaxf(mt1, __shfl_xor_sync(0xffffffffu, mt1, 2));

        const float mn0 = fmaxf(mrow0, mt0);
        const float mn1 = fmaxf(mrow1, mt1);
        const float cr0 = ex2((mrow0 - mn0) * SCALE2);
        const float cr1 = ex2((mrow1 - mn1) * SCALE2);
        const float nm0 = -mn0 * SCALE2;
        const float nm1 = -mn1 * SCALE2;

#pragma unroll
        for (int n = 0; n < 8; n++) {
            s[n][0] = ex2(fmaf(s[n][0], SCALE2, nm0));
            s[n][1] = ex2(fmaf(s[n][1], SCALE2, nm0));
            s[n][2] = ex2(fmaf(s[n][2], SCALE2, nm1));
            s[n][3] = ex2(fmaf(s[n][3], SCALE2, nm1));
        }

        if (!__all_sync(0xffffffffu, (cr0 == 1.f) && (cr1 == 1.f))) {
#pragma unroll
            for (int n = 0; n < 8; n++) {
                o[n][0] *= cr0; o[n][1] *= cr0;
                o[n][2] *= cr1; o[n][3] *= cr1;
            }
        }

        // ---- GEMM2: O += P V (fp16), P from C-frags in-register ----
#pragma unroll
        for (int kg = 0; kg < 4; kg++) {
            unsigned pa[4];
            pa[0] = packh2(s[2 * kg][0],     s[2 * kg][1]);
            pa[1] = packh2(s[2 * kg][2],     s[2 * kg][3]);
            pa[2] = packh2(s[2 * kg + 1][0], s[2 * kg + 1][1]);
            pa[3] = packh2(s[2 * kg + 1][2], s[2 * kg + 1][3]);
#pragma unroll
            for (int nd = 0; nd < 8; nd++) {
                uint2 bb = *(const uint2*)(Vs + (8 * nd + g) * LDVH + 16 * kg + 4 * c);
                mma_f16(o[nd], pa, bb.x, bb.y);
            }
        }

        // ---- deferred row-sum reduction (overlaps GEMM2 latency) ----
        {
            float p0 = 0.f, p1 = 0.f;
#pragma unroll
            for (int n = 0; n < 8; n++) {
                p0 += s[n][0] + s[n][1];
                p1 += s[n][2] + s[n][3];
            }
            p0 += __shfl_xor_sync(0xffffffffu, p0, 1);
            p0 += __shfl_xor_sync(0xffffffffu, p0, 2);
            p1 += __shfl_xor_sync(0xffffffffu, p1, 1);
            p1 += __shfl_xor_sync(0xffffffffu, p1, 2);
            lrow0 = lrow0 * cr0 + p0;
            lrow1 = lrow1 * cr1 + p1;
            mrow0 = mn0;  mrow1 = mn1;
        }

        // ---- stage NEXT tile: V regs->smem, wait K cp.async ----
        if (t + 1 < NT) {
            storeV((__half*)(sm + ((t + 1) & 1) * STAGE_F + KS_F));
            asm volatile("cp.async.wait_group 0;\n" ::: "memory");
        }
        __syncthreads();
    }

    // ---- epilogue: normalize + store ----
    const float inv0 = 1.f / lrow0;
    const float inv1 = 1.f / lrow1;
#pragma unroll
    for (int nd = 0; nd < 8; nd++) {
        const int dcol = 8 * nd + 2 * c;
        float2 w0 = make_float2(o[nd][0] * inv0, o[nd][1] * inv0);
        float2 w1 = make_float2(o[nd][2] * inv1, o[nd][3] * inv1);
        *(float2*)(Og + (size_t)rowA * Dn + dcol) = w0;
        *(float2*)(Og + (size_t)rowB * Dn + dcol) = w1;
    }
}

extern "C" void kernel_launch(void* const* d_in, const int* in_sizes, int n_in,
                              void* d_out, int out_size)
{
    const float* Q = (const float*)d_in[0];
    const float* K = (const float*)d_in[1];
    const float* V = (const float*)d_in[2];
    const void*  M = (const void*)d_in[3];
    float* O = (float*)d_out;

    cudaFuncSetAttribute(attn_mma_kernel,
                         cudaFuncAttributeMaxDynamicSharedMemorySize, SMEM_BYTES);

    probe_mask_kernel<<<1, 256>>>((const unsigned int*)M);
    pack_mask_kernel<<<2048, 256>>>(M);

    dim3 grid(Sn / BM, Bn * Hn);   // (32, 32)
    attn_mma_kernel<<<grid, NTHR, SMEM_BYTES>>>(Q, K, V, O);
}